// round 12
// baseline (speedup 1.0000x reference)
#include <cuda_runtime.h>
#include <math_constants.h>

// ChamferLoss: counting-sort by z + exact pruned NN, R7-shaped engine.
// nn block: 256 queries (32 lanes x PTS=8); 8 warps each scan a 64-candidate
// slice of the block's 512-rank smem window (uniform LDS, 8 ILP chains,
// deferred qsq -> 4 fma-ops/pair). Combine partial mins in smem; per-thread
// radius -> warp-uniform gmem flank scans for exactness (usually empty).

#define B_DIM  8
#define N_PTS  4096
#define NB     512
#define ZMIN   (-4.0f)
#define ZSCALE 64.0f
#define EPS    1e-8f
#define SORT_T 512
#define TPB    256
#define NWARP  8
#define PTS    8
#define QPB    256
#define APAD   128
#define AWIN   (QPB + 2 * APAD)     // 512
#define SLICE  (AWIN / NWARP)       // 64

__device__ float4 g_sorted[2][B_DIM][N_PTS];   // (x, y, z, |c|^2)
__device__ int    g_off[2][B_DIM][NB + 1];

__device__ __forceinline__ int zbucket(float z) {
    int bk = (int)floorf((z - ZMIN) * ZSCALE);
    return min(NB - 1, max(0, bk));
}

__global__ __launch_bounds__(SORT_T) void sort_kernel(
    const float* __restrict__ x1, const float* __restrict__ y1, float* out)
{
    __shared__ int hist[NB];
    __shared__ int offs[NB];
    __shared__ int warpsum[16];

    const int arr = blockIdx.x;
    const int b   = blockIdx.y;
    const float* src = ((arr == 0) ? x1 : y1) + (size_t)b * N_PTS * 3;
    const int tid = threadIdx.x;
    const int lane = tid & 31;
    const int wid  = tid >> 5;

    if (arr == 0 && b == 0 && tid == 0) out[0] = 0.0f;

    hist[tid] = 0;
    __syncthreads();

    for (int i = tid; i < N_PTS; i += SORT_T)
        atomicAdd(&hist[zbucket(src[i * 3 + 2])], 1);
    __syncthreads();

    // 3-barrier scan: warp shuffle inclusive scan + warp-sum scan
    int v = hist[tid];
    #pragma unroll
    for (int d = 1; d < 32; d <<= 1) {
        int n = __shfl_up_sync(0xFFFFFFFFu, v, d);
        if (lane >= d) v += n;
    }
    if (lane == 31) warpsum[wid] = v;
    __syncthreads();
    if (wid == 0 && lane < 16) {
        int s = warpsum[lane];
        #pragma unroll
        for (int d = 1; d < 16; d <<= 1) {
            int n = __shfl_up_sync(0xFFFFu, s, d);
            if (lane >= d) s += n;
        }
        warpsum[lane] = s;
    }
    __syncthreads();
    const int add = (wid > 0) ? warpsum[wid - 1] : 0;
    offs[tid] = v + add - hist[tid];      // exclusive prefix
    g_off[arr][b][tid] = offs[tid];
    if (tid == 0) g_off[arr][b][NB] = N_PTS;
    hist[tid] = 0;                        // reuse as running counters
    __syncthreads();

    float4* dst = g_sorted[arr][b];
    for (int i = tid; i < N_PTS; i += SORT_T) {
        const float x = src[i * 3 + 0];
        const float y = src[i * 3 + 1];
        const float z = src[i * 3 + 2];
        const int bk  = zbucket(z);
        const int pos = offs[bk] + atomicAdd(&hist[bk], 1);
        dst[pos] = make_float4(x, y, z, fmaf(x, x, fmaf(y, y, z * z)));
    }
}

__global__ __launch_bounds__(TPB) void nn_kernel(float* out, float scale)
{
    __shared__ float4 sC[AWIN];              // 8KB candidate window
    __shared__ float  sPart[NWARP][QPB];     // 8KB partial mins
    __shared__ int    soff[NB + 1];
    __shared__ float  wsum[NWARP];

    const int dir = blockIdx.z;
    const int b   = blockIdx.y;
    const float4* __restrict__ Ca = g_sorted[1 - dir][b];
    const int* __restrict__ goff  = g_off[1 - dir][b];

    const int tid = threadIdx.x;
    const int u   = tid & 31;
    const int w   = tid >> 5;
    const int Q0  = blockIdx.x * QPB;

    for (int i = tid; i <= NB; i += TPB) soff[i] = goff[i];

    const int A0 = max(Q0 - APAD, 0);
    const int A1 = min(Q0 + QPB + APAD, N_PTS);
    const int an = A1 - A0;
    for (int i = tid; i < an; i += TPB) sC[i] = Ca[A0 + i];

    // 8 queries per lane (same set for every warp); qsq deferred
    float nx[PTS], ny[PTS], nz[PTS], mn[PTS];
    #pragma unroll
    for (int k = 0; k < PTS; ++k) {
        const float4 m = g_sorted[dir][b][Q0 + u + k * 32];
        nx[k] = -2.0f * m.x;
        ny[k] = -2.0f * m.y;
        nz[k] = -2.0f * m.z;
        mn[k] = CUDART_INF_F;
    }
    __syncthreads();

    // stage A: warp w scans its 64-candidate slice for all 256 queries
    const int slo = min(w * SLICE, an);
    const int shi = min(slo + SLICE, an);
    #pragma unroll 2
    for (int j = slo; j < shi; ++j) {
        const float4 c = sC[j];
        #pragma unroll
        for (int k = 0; k < PTS; ++k) {
            float t = fmaf(nz[k], c.z, c.w);     // g = -2q.c + |c|^2
            t = fmaf(ny[k], c.y, t);
            t = fmaf(nx[k], c.x, t);
            mn[k] = fminf(mn[k], t);
        }
    }

    // publish and combine
    #pragma unroll
    for (int k = 0; k < PTS; ++k) sPart[w][u + k * 32] = mn[k];
    __syncthreads();

    float bestp = sPart[0][tid];
    #pragma unroll
    for (int ww = 1; ww < NWARP; ++ww) bestp = fminf(bestp, sPart[ww][tid]);

    // thread tid now owns query Q0+tid
    const float4 me = g_sorted[dir][b][Q0 + tid];
    const float qsq = me.w;
    const float r = sqrtf(fmaxf(bestp + qsq, 0.0f)) * 1.001f + 1e-3f;

    float wlo = me.z - r;
    float whi = me.z + r;
    #pragma unroll
    for (int off = 16; off > 0; off >>= 1) {
        wlo = fminf(wlo, __shfl_xor_sync(0xFFFFFFFFu, wlo, off));
        whi = fmaxf(whi, __shfl_xor_sync(0xFFFFFFFFu, whi, off));
    }
    const int wL = soff[zbucket(wlo)];          // warp-uniform
    const int wR = soff[zbucket(whi) + 1];

    // stage B: flank scans outside [A0, A1) — usually empty
    const float nqx = -2.0f * me.x;
    const float nqy = -2.0f * me.y;
    const float nqz = -2.0f * me.z;
    for (int j = wL; j < A0; ++j) {
        const float4 c = Ca[j];
        float t = fmaf(nqz, c.z, c.w);
        t = fmaf(nqy, c.y, t);
        t = fmaf(nqx, c.x, t);
        bestp = fminf(bestp, t);
    }
    for (int j = A1; j < wR; ++j) {
        const float4 c = Ca[j];
        float t = fmaf(nqz, c.z, c.w);
        t = fmaf(nqy, c.y, t);
        t = fmaf(nqx, c.x, t);
        bestp = fminf(bestp, t);
    }

    float v = sqrtf(fmaxf(bestp + qsq, 0.0f) + EPS);

    #pragma unroll
    for (int off = 16; off > 0; off >>= 1)
        v += __shfl_xor_sync(0xFFFFFFFFu, v, off);

    if (u == 0) wsum[w] = v;
    __syncthreads();
    if (tid == 0) {
        float t = 0.0f;
        #pragma unroll
        for (int ww = 0; ww < NWARP; ++ww) t += wsum[ww];
        atomicAdd(out, t * scale);
    }
}

extern "C" void kernel_launch(void* const* d_in, const int* in_sizes, int n_in,
                              void* d_out, int out_size)
{
    const float* x1 = (const float*)d_in[0];
    const float* y1 = (const float*)d_in[1];
    float* out = (float*)d_out;

    sort_kernel<<<dim3(2, B_DIM), SORT_T>>>(x1, y1, out);

    const float scale = 1.0f / (float)(B_DIM * N_PTS);
    nn_kernel<<<dim3(N_PTS / QPB, B_DIM, 2), TPB>>>(out, scale);
}

// round 13
// speedup vs baseline: 1.2345x; 1.2345x over previous
#include <cuda_runtime.h>
#include <math_constants.h>

// ChamferLoss: counting-sort by z + exact windowed NN using R7's proven engine.
// nn block: 256 queries (32 lanes x PTS=8, coeffs in regs); candidate window =
// 768 sorted ranks [Q0-256, Q0+512+256) in smem; 8 warps x 96-candidate slices,
// quad-batched uniform LDS.128, deferred qsq -> 4 fma-ops/pair.
// Exactness: r from window best; flank-scan [z-r,z+r] outside the window (rare).

#define B_DIM  8
#define N_PTS  4096
#define NB     512
#define ZMIN   (-4.0f)
#define ZSCALE 64.0f
#define EPS    1e-8f
#define SORT_T 512
#define TPB    256
#define NWARP  8
#define PTS    8
#define QPB    256
#define WPAD   256
#define WMAX   (QPB + 2 * WPAD)   // 768

__device__ float4 g_sorted[2][B_DIM][N_PTS];   // (x, y, z, |c|^2)
__device__ int    g_off[2][B_DIM][NB + 1];

__device__ __forceinline__ int zbucket(float z) {
    int bk = (int)floorf((z - ZMIN) * ZSCALE);
    return min(NB - 1, max(0, bk));
}

__global__ __launch_bounds__(SORT_T) void sort_kernel(
    const float* __restrict__ x1, const float* __restrict__ y1, float* out)
{
    __shared__ int hist[NB];
    __shared__ int offs[NB];
    __shared__ int warpsum[16];

    const int arr = blockIdx.x;
    const int b   = blockIdx.y;
    const float* src = ((arr == 0) ? x1 : y1) + (size_t)b * N_PTS * 3;
    const int tid = threadIdx.x;
    const int lane = tid & 31;
    const int wid  = tid >> 5;

    if (arr == 0 && b == 0 && tid == 0) out[0] = 0.0f;

    hist[tid] = 0;
    __syncthreads();

    for (int i = tid; i < N_PTS; i += SORT_T)
        atomicAdd(&hist[zbucket(src[i * 3 + 2])], 1);
    __syncthreads();

    int v = hist[tid];
    #pragma unroll
    for (int d = 1; d < 32; d <<= 1) {
        int n = __shfl_up_sync(0xFFFFFFFFu, v, d);
        if (lane >= d) v += n;
    }
    if (lane == 31) warpsum[wid] = v;
    __syncthreads();
    if (wid == 0 && lane < 16) {
        int s = warpsum[lane];
        #pragma unroll
        for (int d = 1; d < 16; d <<= 1) {
            int n = __shfl_up_sync(0xFFFFu, s, d);
            if (lane >= d) s += n;
        }
        warpsum[lane] = s;
    }
    __syncthreads();
    const int add = (wid > 0) ? warpsum[wid - 1] : 0;
    offs[tid] = v + add - hist[tid];
    g_off[arr][b][tid] = offs[tid];
    if (tid == 0) g_off[arr][b][NB] = N_PTS;
    hist[tid] = 0;
    __syncthreads();

    float4* dst = g_sorted[arr][b];
    for (int i = tid; i < N_PTS; i += SORT_T) {
        const float x = src[i * 3 + 0];
        const float y = src[i * 3 + 1];
        const float z = src[i * 3 + 2];
        const int bk  = zbucket(z);
        const int pos = offs[bk] + atomicAdd(&hist[bk], 1);
        dst[pos] = make_float4(x, y, z, fmaf(x, x, fmaf(y, y, z * z)));
    }
}

__global__ __launch_bounds__(TPB, 2) void nn_kernel(float* out, float scale)
{
    __shared__ float4 sC[WMAX];              // 12KB candidate window
    __shared__ float  sPart[NWARP][QPB];     // 8KB
    __shared__ int    soff[NB + 1];
    __shared__ float  wsum[NWARP];

    const int dir = blockIdx.z;
    const int b   = blockIdx.y;
    const float4* __restrict__ Ca = g_sorted[1 - dir][b];
    const int* __restrict__ goff  = g_off[1 - dir][b];

    const int tid = threadIdx.x;
    const int u   = tid & 31;
    const int w   = tid >> 5;
    const int Q0  = blockIdx.x * QPB;

    for (int i = tid; i <= NB; i += TPB) soff[i] = goff[i];

    const int A0 = max(Q0 - WPAD, 0);
    const int A1 = min(Q0 + QPB + WPAD, N_PTS);
    const int an = A1 - A0;                  // multiple of 32
    for (int i = tid; i < an; i += TPB) sC[i] = Ca[A0 + i];

    // 8 queries per lane (same 256 for every warp); qsq deferred
    float nx[PTS], ny[PTS], nz[PTS], mn[PTS];
    #pragma unroll
    for (int k = 0; k < PTS; ++k) {
        const float4 m = g_sorted[dir][b][Q0 + u + k * 32];
        nx[k] = -2.0f * m.x;
        ny[k] = -2.0f * m.y;
        nz[k] = -2.0f * m.z;
        mn[k] = CUDART_INF_F;
    }
    __syncthreads();

    // stage A: warp w scans its slice, quad-batched (R7 inner-loop shape)
    const int sl  = an / NWARP;              // 96 or 64, multiple of 4
    const int slo = w * sl;
    const int shi = slo + sl;
    for (int j = slo; j < shi; j += 4) {
        float4 C0 = sC[j + 0];
        float4 C1 = sC[j + 1];
        float4 C2 = sC[j + 2];
        float4 C3 = sC[j + 3];
        #pragma unroll
        for (int k = 0; k < PTS; ++k) {
            float t0 = fmaf(nz[k], C0.z, C0.w);
            float t1 = fmaf(nz[k], C1.z, C1.w);
            float t2 = fmaf(nz[k], C2.z, C2.w);
            float t3 = fmaf(nz[k], C3.z, C3.w);
            t0 = fmaf(ny[k], C0.y, t0);  t1 = fmaf(ny[k], C1.y, t1);
            t2 = fmaf(ny[k], C2.y, t2);  t3 = fmaf(ny[k], C3.y, t3);
            t0 = fmaf(nx[k], C0.x, t0);  t1 = fmaf(nx[k], C1.x, t1);
            t2 = fmaf(nx[k], C2.x, t2);  t3 = fmaf(nx[k], C3.x, t3);
            mn[k] = fminf(mn[k], fminf(fminf(t0, t1), fminf(t2, t3)));
        }
    }

    #pragma unroll
    for (int k = 0; k < PTS; ++k) sPart[w][u + k * 32] = mn[k];
    __syncthreads();

    // combine: thread tid owns query Q0+tid (deferred form)
    float bestg = sPart[0][tid];
    #pragma unroll
    for (int ww = 1; ww < NWARP; ++ww) bestg = fminf(bestg, sPart[ww][tid]);

    const float4 me = g_sorted[dir][b][Q0 + tid];
    const float qsq = me.w;
    const float r = sqrtf(fmaxf(bestg + qsq, 0.0f)) * 1.001f + 1e-3f;

    // warp-uniform flank range from [z-r, z+r]
    float flz = me.z - r;
    float frz = me.z + r;
    #pragma unroll
    for (int off = 16; off > 0; off >>= 1) {
        flz = fminf(flz, __shfl_xor_sync(0xFFFFFFFFu, flz, off));
        frz = fmaxf(frz, __shfl_xor_sync(0xFFFFFFFFu, frz, off));
    }
    const int FL = soff[zbucket(flz)];
    const int FR = soff[zbucket(frz) + 1];

    const float nqx = -2.0f * me.x;
    const float nqy = -2.0f * me.y;
    const float nqz = -2.0f * me.z;
    for (int j = FL; j < A0; ++j) {          // usually empty
        const float4 c = Ca[j];
        float t = fmaf(nqz, c.z, c.w);
        t = fmaf(nqy, c.y, t);
        t = fmaf(nqx, c.x, t);
        bestg = fminf(bestg, t);
    }
    for (int j = A1; j < FR; ++j) {          // usually empty
        const float4 c = Ca[j];
        float t = fmaf(nqz, c.z, c.w);
        t = fmaf(nqy, c.y, t);
        t = fmaf(nqx, c.x, t);
        bestg = fminf(bestg, t);
    }

    float v = sqrtf(fmaxf(bestg + qsq, 0.0f) + EPS);

    #pragma unroll
    for (int off = 16; off > 0; off >>= 1)
        v += __shfl_xor_sync(0xFFFFFFFFu, v, off);

    if (u == 0) wsum[w] = v;
    __syncthreads();
    if (tid == 0) {
        float t = 0.0f;
        #pragma unroll
        for (int ww = 0; ww < NWARP; ++ww) t += wsum[ww];
        atomicAdd(out, t * scale);
    }
}

extern "C" void kernel_launch(void* const* d_in, const int* in_sizes, int n_in,
                              void* d_out, int out_size)
{
    const float* x1 = (const float*)d_in[0];
    const float* y1 = (const float*)d_in[1];
    float* out = (float*)d_out;

    sort_kernel<<<dim3(2, B_DIM), SORT_T>>>(x1, y1, out);

    const float scale = 1.0f / (float)(B_DIM * N_PTS);
    nn_kernel<<<dim3(N_PTS / QPB, B_DIM, 2), TPB>>>(out, scale);
}

// round 14
// speedup vs baseline: 2.0699x; 1.6767x over previous
#include <cuda_runtime.h>
#include <math_constants.h>

// ChamferLoss fused-direction kernel (R7 engine) + transposed partials so that
// pass2 is 1-2 coalesced float4 loads per thread (L2-resident) instead of
// 4-8 scalar strided loads.
// Each unique (x,y) pair evaluated ONCE: d2 = -2 x.y + (|x|^2 + |y|^2)
// -> 4 fma-pipe ops/pair (3 FFMA + 1 FADD) + 2 FMNMX (alu). Measured at ~93%
// of the fma-port floor. xmin[q] in registers; ymin[c] in shared via rotating
// quad ownership. Per-block partials to exclusive __device__ slots.

#define B_DIM  8
#define N_PTS  4096
#define TPB    256
#define NWARP  8
#define PTS    16                 // queries per thread
#define QPB    512                // queries per block (32 lanes * PTS)
#define NQB    (N_PTS / QPB)      // 8 query blocks
#define CSPLIT 4
#define CPB    (N_PTS / CSPLIT)   // 1024 candidates per block
#define CPW    (CPB / NWARP)      // 128 candidates per warp
#define NQUAD  (CPW / 4)          // 32 quads per warp
#define EPS    1e-8f

__device__ float g_xpart[B_DIM][N_PTS][CSPLIT];  // [b][q][z]  (16B rows)
__device__ float g_ypart[B_DIM][N_PTS][NQB];     // [b][c][qb] (32B rows)

__global__ __launch_bounds__(TPB, 2) void chamfer_main(
    const float* __restrict__ x1, const float* __restrict__ y1,
    float* __restrict__ out)
{
    __shared__ float4 sC[CPB];            // (-2rx,-2ry,-2rz,rsq): 16KB
    __shared__ float  sY[CPB];            // ymin partials (warp-exclusive ranges)
    __shared__ float  sPart[NWARP][QPB];  // xmin partials: 16KB

    const int b     = blockIdx.y;
    const int qb    = blockIdx.x;
    const int qbase = qb * QPB;
    const int cbase = blockIdx.z * CPB;
    const float* Qb = x1 + (size_t)b * N_PTS * 3;
    const float* Rb = y1 + (size_t)b * N_PTS * 3;

    const int tid = threadIdx.x;
    const int u   = tid & 31;
    const int w   = tid >> 5;

    if (qb == 0 && b == 0 && blockIdx.z == 0 && tid == 0) out[0] = 0.0f;

    // tile fill: candidate record = (-2rx, -2ry, -2rz, rsq)
    for (int i = tid; i < CPB; i += TPB) {
        const float* r = Rb + (size_t)(cbase + i) * 3;
        const float rx = r[0], ry = r[1], rz = r[2];
        sC[i] = make_float4(-2.0f * rx, -2.0f * ry, -2.0f * rz,
                            fmaf(rx, rx, fmaf(ry, ry, rz * rz)));
        sY[i] = CUDART_INF_F;
    }

    // 16 queries per thread
    float qx[PTS], qy[PTS], qz[PTS], xsq[PTS], mn[PTS];
    #pragma unroll
    for (int k = 0; k < PTS; ++k) {
        const int p = qbase + u + k * 32;
        qx[k] = Qb[p * 3 + 0];
        qy[k] = Qb[p * 3 + 1];
        qz[k] = Qb[p * 3 + 2];
        xsq[k] = fmaf(qx[k], qx[k], fmaf(qy[k], qy[k], qz[k] * qz[k]));
        mn[k] = CUDART_INF_F;
    }
    __syncthreads();

    // rotating quad ownership: at step s, lane u owns quad (u+s)&31 of warp w's
    // 128-candidate slice. Converged warp => sequential steps => race-free sY rmw.
    const int wslice = w * CPW;
    for (int s = 0; s < NQUAD; ++s) {
        const int qd   = (u + s) & (NQUAD - 1);
        const int cidx = wslice + qd * 4;

        float4 C[4];
        #pragma unroll
        for (int c = 0; c < 4; ++c) C[c] = sC[cidx + c];

        float my[4];
        #pragma unroll
        for (int c = 0; c < 4; ++c) my[c] = sY[cidx + c];

        #pragma unroll
        for (int c = 0; c < 4; ++c) {
            const float c0 = C[c].x, c1 = C[c].y, c2 = C[c].z, rsq = C[c].w;
            float ml = my[c];
            #pragma unroll
            for (int k = 0; k < PTS; ++k) {
                const float S = xsq[k] + rsq;        // 1 FADD
                float t = fmaf(c2, qz[k], S);        // 3 FFMA
                t = fmaf(c1, qy[k], t);
                t = fmaf(c0, qx[k], t);
                mn[k] = fminf(mn[k], t);             // 2 FMNMX (alu)
                ml    = fminf(ml, t);
            }
            my[c] = ml;
        }

        #pragma unroll
        for (int c = 0; c < 4; ++c) sY[cidx + c] = my[c];
    }

    // publish xmin partials
    #pragma unroll
    for (int k = 0; k < PTS; ++k) sPart[w][u + k * 32] = mn[k];
    __syncthreads();

    // combine xmin across warps -> exclusive transposed slot
    for (int q = tid; q < QPB; q += TPB) {
        float m = sPart[0][q];
        #pragma unroll
        for (int ww = 1; ww < NWARP; ++ww) m = fminf(m, sPart[ww][q]);
        g_xpart[b][qbase + q][blockIdx.z] = m;
    }
    // ymin -> exclusive transposed slot
    for (int i = tid; i < CPB; i += TPB)
        g_ypart[b][cbase + i][qb] = sY[i];
}

__global__ void pass2_kernel(float* out, float scale) {
    __shared__ float wsum[8];
    const int i = blockIdx.x * blockDim.x + threadIdx.x;   // 0 .. 65535
    float v;
    if (i < B_DIM * N_PTS) {
        // x side: one coalesced float4 load
        const int b = i >> 12, q = i & 4095;
        const float4 p = *reinterpret_cast<const float4*>(&g_xpart[b][q][0]);
        const float m = fminf(fminf(p.x, p.y), fminf(p.z, p.w));
        v = sqrtf(fmaxf(m, 0.0f) + EPS);
    } else {
        // y side: two coalesced float4 loads
        const int j = i - B_DIM * N_PTS;
        const int b = j >> 12, c = j & 4095;
        const float4 p0 = *reinterpret_cast<const float4*>(&g_ypart[b][c][0]);
        const float4 p1 = *reinterpret_cast<const float4*>(&g_ypart[b][c][4]);
        const float m0 = fminf(fminf(p0.x, p0.y), fminf(p0.z, p0.w));
        const float m1 = fminf(fminf(p1.x, p1.y), fminf(p1.z, p1.w));
        v = sqrtf(fmaxf(fminf(m0, m1), 0.0f) + EPS);
    }

    #pragma unroll
    for (int off = 16; off > 0; off >>= 1)
        v += __shfl_xor_sync(0xFFFFFFFFu, v, off);

    const int u = threadIdx.x & 31;
    const int w = threadIdx.x >> 5;
    if (u == 0) wsum[w] = v;
    __syncthreads();
    if (threadIdx.x == 0) {
        float t = 0.0f;
        #pragma unroll
        for (int ww = 0; ww < 8; ++ww) t += wsum[ww];
        atomicAdd(out, t * scale);
    }
}

extern "C" void kernel_launch(void* const* d_in, const int* in_sizes, int n_in,
                              void* d_out, int out_size)
{
    const float* x1 = (const float*)d_in[0];
    const float* y1 = (const float*)d_in[1];
    float* out = (float*)d_out;

    dim3 grid(NQB, B_DIM, CSPLIT);   // (8, 8, 4) = 256 blocks x 8 warps
    chamfer_main<<<grid, TPB>>>(x1, y1, out);

    const float scale = 1.0f / (float)(B_DIM * N_PTS);
    pass2_kernel<<<(2 * B_DIM * N_PTS) / 256, 256>>>(out, scale);
}